// round 4
// baseline (speedup 1.0000x reference)
#include <cuda_runtime.h>

#define GRID 296
#define TPB  1024

// Packed params: [0:30) W1, [30:33) b1, [33:36) gamma, [36:39) beta,
// [39:45) m, [45:51) theta, [51:59) g2, [59:67) bt2, [67:147) W2, [147:157) b2
__constant__ float cP[157];
__device__ float g_pack[157];

#define W1c(i)  cP[(i)]
#define B1c(i)  cP[30 + (i)]
#define GAMc(i) cP[33 + (i)]
#define BETc(i) cP[36 + (i)]
#define Mc(i)   cP[39 + (i)]
#define THc(i)  cP[45 + (i)]
#define G2c(i)  cP[51 + (i)]
#define BT2c(i) cP[59 + (i)]
#define W2c(i)  cP[67 + (i)]
#define B2c(i)  cP[147 + (i)]

__device__ unsigned g_counter = 0;          // monotone ticket counter (replay-safe)
__device__ float g_partials[GRID * 16];     // [block][8 sums, 8 sumsq]

__device__ __forceinline__ float ex2f(float x) {
    float y; asm("ex2.approx.ftz.f32 %0, %1;" : "=f"(y) : "f"(x)); return y;
}
__device__ __forceinline__ float sin_fast(float x) {
    float y; asm("sin.approx.ftz.f32 %0, %1;" : "=f"(y) : "f"(x)); return y;
}

__global__ void pack_kernel(const float* __restrict__ W1, const float* __restrict__ b1,
                            const float* __restrict__ gam, const float* __restrict__ bet,
                            const float* __restrict__ m, const float* __restrict__ th,
                            const float* __restrict__ g2, const float* __restrict__ bt2,
                            const float* __restrict__ W2, const float* __restrict__ b2)
{
    const int t = threadIdx.x;
    if      (t < 30)  g_pack[t] = W1[t];
    else if (t < 33)  g_pack[t] = b1[t - 30];
    else if (t < 36)  g_pack[t] = gam[t - 33];
    else if (t < 39)  g_pack[t] = bet[t - 36];
    else if (t < 45)  g_pack[t] = m[t - 39];
    else if (t < 51)  g_pack[t] = th[t - 45];
    else if (t < 59)  g_pack[t] = g2[t - 51];
    else if (t < 67)  g_pack[t] = bt2[t - 59];
    else if (t < 147) g_pack[t] = W2[t - 67];
    else if (t < 157) g_pack[t] = b2[t - 147];
}

// Recompute the 6 (transformed) memberships from cached hn
__device__ __forceinline__ void memberships(const float h0, const float h1, const float h2,
                                            float* __restrict__ p)
{
    const float C2 = 0.99999f * 0.99999f;
    const float hn[3] = {h0, h1, h2};
#pragma unroll
    for (int q = 0; q < 3; q++)
#pragma unroll
        for (int j = 0; j < 2; j++) {
            const int k = q * 2 + j;
            const float th = THc(k);
            const float c2 = -1.4426950408889634f / (2.0f * th * th);
            const float a = hn[q] - Mc(k);
            const float f = ex2f(a * a * c2);
            const float pv = fminf(f + 1e-16f, C2);
            p[k] = (q == 0) ? pv : (1.0f - pv);
        }
}

__global__ __launch_bounds__(TPB, 2)
void qfnn_kernel(const float* __restrict__ xg, float* __restrict__ outg,
                 int n, int rpb)
{
    extern __shared__ float sm[];
    float* ps  = sm;                 // 3*rpb : cached hn values (3 planes)
    float* red = sm + 3 * rpb;       // 512   : reduction / chunk scratch
    float* s2s = red + 512;          // 8
    float* t2s = s2s + 8;            // 8
    float* b2p = t2s + 8;            // 4

    const int bid = blockIdx.x, tid = threadIdx.x;
    const int row0 = bid * rpb;
    int nrows = n - row0;
    if (nrows > rpb) nrows = rpb;
    if (nrows < 0) nrows = 0;

    const int ntiles = (nrows + TPB - 1) / TPB;

    // ---------------- Pass 1: x -> hn (cached in smem) ----------------
    for (int t = 0; t < ntiles; t++) {
        const int r = t * TPB + tid;
        if (r < nrows) {
            const float2* xp = (const float2*)(xg + (size_t)(row0 + r) * 10);
            const float2 v0 = xp[0], v1 = xp[1], v2 = xp[2], v3 = xp[3], v4 = xp[4];
            const float xv[10] = {v0.x, v0.y, v1.x, v1.y, v2.x,
                                  v2.y, v3.x, v3.y, v4.x, v4.y};
            float h[3];
#pragma unroll
            for (int q = 0; q < 3; q++) {
                float a = B1c(q);
#pragma unroll
                for (int k = 0; k < 10; k++) a = fmaf(xv[k], W1c(q * 10 + k), a);
                h[q] = a;
            }
            const float mu = (h[0] + h[1] + h[2]) * (1.0f / 3.0f);
            const float d0 = h[0] - mu, d1 = h[1] - mu, d2 = h[2] - mu;
            const float var = (d0 * d0 + d1 * d1 + d2 * d2) * (1.0f / 3.0f);
            const float rn = rsqrtf(var + 1e-5f);
            ps[0 * rpb + r] = fmaf(d0 * rn, GAMc(0), BETc(0));
            ps[1 * rpb + r] = fmaf(d1 * rn, GAMc(1), BETc(1));
            ps[2 * rpb + r] = fmaf(d2 * rn, GAMc(2), BETc(2));
        }
    }

    // ---------------- Pass 1.5: hn -> channel sums ----------------
    float accS[8], accQ[8];
#pragma unroll
    for (int c = 0; c < 8; c++) { accS[c] = 0.f; accQ[c] = 0.f; }

    for (int t = 0; t < ntiles; t++) {
        const int r = t * TPB + tid;
        if (r < nrows) {
            float p[6];
            memberships(ps[0 * rpb + r], ps[1 * rpb + r], ps[2 * rpb + r], p);
            const float w00 = p[2] * p[4], w01 = p[2] * p[5];
            const float w10 = p[3] * p[4], w11 = p[3] * p[5];
            float o[8];
            o[0] = p[0] * w00; o[1] = p[0] * w01; o[2] = p[0] * w10; o[3] = p[0] * w11;
            o[4] = p[1] * w00; o[5] = p[1] * w01; o[6] = p[1] * w10; o[7] = p[1] * w11;
#pragma unroll
            for (int c = 0; c < 8; c++) {
                accS[c] += o[c];
                accQ[c] = fmaf(o[c], o[c], accQ[c]);
            }
        }
    }

    // ---------------- Block reduction (deterministic) ----------------
    {
        const int lane = tid & 31, wrp = tid >> 5;
#pragma unroll
        for (int k = 0; k < 16; k++) {
            float v = (k < 8) ? accS[k] : accQ[k - 8];
#pragma unroll
            for (int off = 16; off; off >>= 1)
                v += __shfl_down_sync(0xffffffffu, v, off);
            if (lane == 0) red[wrp * 16 + k] = v;
        }
    }
    __syncthreads();
    if (tid < 16) {
        float s = 0.f;
#pragma unroll
        for (int w = 0; w < TPB / 32; w++) s += red[w * 16 + tid];
        g_partials[bid * 16 + tid] = s;
        __threadfence();
    }
    __syncthreads();

    // ---------------- Grid barrier (ticketed, replay-safe) ----------------
    if (tid == 0) {
        __threadfence();
        const unsigned tk = atomicAdd(&g_counter, 1u);
        const unsigned target = (tk / GRID + 1u) * GRID;
        while (*((volatile unsigned*)&g_counter) < target) { }
    }
    __syncthreads();
    __threadfence();

    // ---------------- Finalize BN constants ----------------
    if (tid < 256) {
        const int met = tid & 15, ch = tid >> 4;
        float s = 0.f;
        for (int b = ch; b < GRID; b += 16)
            s += __ldcg(&g_partials[b * 16 + met]);
        red[tid] = s;
    }
    __syncthreads();
    if (tid < 16) {
        float s = 0.f;
#pragma unroll
        for (int w = 0; w < 16; w++) s += red[w * 16 + tid];
        red[256 + tid] = s;
    }
    __syncthreads();
    if (tid < 8) {
        const float invB = 1.0f / (float)n;
        const float muv = red[256 + tid] * invB;
        const float msq = red[256 + tid + 8] * invB;
        const float var = msq - muv * muv;
        const float sc = G2c(tid) * rsqrtf(var + 1e-5f);
        s2s[tid] = sc;
        t2s[tid] = BT2c(tid) - muv * sc;
    }
    __syncthreads();
    if (tid < 3) {
        float a = B2c(tid);
#pragma unroll
        for (int c = 0; c < 8; c++) a = fmaf(t2s[c], W2c(tid * 8 + c), a);
        b2p[tid] = a;
    }
    __syncthreads();

    // ---------------- Pass 2: hn -> memberships -> logits -> result ----------------
    for (int t = 0; t < ntiles; t++) {
        const int r = t * TPB + tid;
        if (r < nrows) {
            float p[6];
            memberships(ps[0 * rpb + r], ps[1 * rpb + r], ps[2 * rpb + r], p);
            const float w00 = p[2] * p[4], w01 = p[2] * p[5];
            const float w10 = p[3] * p[4], w11 = p[3] * p[5];
            float u[8];
            u[0] = p[0] * w00 * s2s[0]; u[1] = p[0] * w01 * s2s[1];
            u[2] = p[0] * w10 * s2s[2]; u[3] = p[0] * w11 * s2s[3];
            u[4] = p[1] * w00 * s2s[4]; u[5] = p[1] * w01 * s2s[5];
            u[6] = p[1] * w10 * s2s[6]; u[7] = p[1] * w11 * s2s[7];
            float lg[3];
#pragma unroll
            for (int i = 0; i < 3; i++) {
                float a = b2p[i];
#pragma unroll
                for (int c = 0; c < 8; c++) a = fmaf(u[c], W2c(i * 8 + c), a);
                lg[i] = a;
            }
            const float sg0 = sin_fast(lg[0] * 0.5f);
            const float sg1 = sin_fast(lg[1] * 0.5f);
            const float sg2 = sin_fast(lg[2] * 0.5f);
            const float pq0 = sg0 * sg0, pq1 = sg1 * sg1, pq2 = sg2 * sg2;
            const float cq0 = 1.f - pq0, cq1 = 1.f - pq1, cq2 = 1.f - pq2;
            const float tt = cq1 * cq2;
            float* dst = outg + (size_t)(row0 + r) * 3;
            dst[0] = cq0 * tt;
            dst[1] = pq0 * tt;
            dst[2] = cq0 * (pq1 * cq2);
        }
    }
}

extern "C" void kernel_launch(void* const* d_in, const int* in_sizes, int n_in,
                              void* d_out, int out_size)
{
    const float* x = (const float*)d_in[0];

    pack_kernel<<<1, 157, 0, 0>>>(
        (const float*)d_in[1], (const float*)d_in[2], (const float*)d_in[3],
        (const float*)d_in[4], (const float*)d_in[5], (const float*)d_in[6],
        (const float*)d_in[7], (const float*)d_in[8], (const float*)d_in[9],
        (const float*)d_in[10]);

    void* packAddr = nullptr;
    cudaGetSymbolAddress(&packAddr, g_pack);
    cudaMemcpyToSymbolAsync(cP, packAddr, 157 * sizeof(float), 0,
                            cudaMemcpyDeviceToDevice, 0);

    const int n = in_sizes[0] / 10;                 // 1048576
    const int rpb = (n + GRID - 1) / GRID;          // 3543
    const size_t smem = (size_t)(3 * rpb + 512 + 20) * sizeof(float);
    cudaFuncSetAttribute(qfnn_kernel, cudaFuncAttributeMaxDynamicSharedMemorySize, (int)smem);
    qfnn_kernel<<<GRID, TPB, smem, 0>>>(x, (float*)d_out, n, rpb);
}

// round 5
// speedup vs baseline: 1.3366x; 1.3366x over previous
#include <cuda_runtime.h>

#define GRID 148
#define TPB  1024

__device__ unsigned g_counter = 0;          // monotone ticket counter (replay-safe)
__device__ float g_partials[GRID * 16];     // [block][8 sums, 8 sumsq]

__device__ __forceinline__ float ex2f(float x) {
    float y; asm("ex2.approx.ftz.f32 %0, %1;" : "=f"(y) : "f"(x)); return y;
}
__device__ __forceinline__ float sin_fast(float x) {
    float y; asm("sin.approx.ftz.f32 %0, %1;" : "=f"(y) : "f"(x)); return y;
}
__device__ __forceinline__ float2 fma2(float2 a, float2 b, float2 c) {
    float2 d;
    asm("fma.rn.f32x2 %0, %1, %2, %3;"
        : "=l"(*(unsigned long long*)&d)
        : "l"(*(unsigned long long*)&a), "l"(*(unsigned long long*)&b),
          "l"(*(unsigned long long*)&c));
    return d;
}
__device__ __forceinline__ float2 mul2(float2 a, float2 b) {
    float2 d;
    asm("mul.rn.f32x2 %0, %1, %2;"
        : "=l"(*(unsigned long long*)&d)
        : "l"(*(unsigned long long*)&a), "l"(*(unsigned long long*)&b));
    return d;
}
__device__ __forceinline__ float2 add2(float2 a, float2 b) {
    float2 d;
    asm("add.rn.f32x2 %0, %1, %2;"
        : "=l"(*(unsigned long long*)&d)
        : "l"(*(unsigned long long*)&a), "l"(*(unsigned long long*)&b));
    return d;
}
__device__ __forceinline__ float2 splat(float v) { return make_float2(v, v); }

// smem param layout (float indices)
#define PW1  0     // 30  (pairs at even base 0)
#define PW2  32    // 80  (pairs at even base 32)
#define PB1  112   // 3
#define PGAM 115   // 3
#define PBET 118   // 3
#define PM   121   // 6
#define PTH  127   // 6
#define PG2  133   // 8
#define PBT2 141   // 8
#define PB2  149   // 3
#define PRM_SZ 160

__global__ __launch_bounds__(TPB, 1)
void qfnn_kernel(const float* __restrict__ xg, float* __restrict__ outg,
                 const float* __restrict__ W1, const float* __restrict__ b1,
                 const float* __restrict__ gam, const float* __restrict__ bet,
                 const float* __restrict__ mIn, const float* __restrict__ th,
                 const float* __restrict__ g2, const float* __restrict__ bt2,
                 const float* __restrict__ W2, const float* __restrict__ b2,
                 int n, int rpb)
{
    extern __shared__ float sm[];
    float* prm = sm;                    // 160
    float* red = sm + PRM_SZ;           // 512
    float* s2s = red + 512;             // 8 (even offset -> float2-aligned)
    float* t2s = s2s + 8;               // 8
    float* b2p = t2s + 8;               // 8 (pad)
    float* ps  = b2p + 8;               // 6*rpb floats = 3 float2 planes
    float2* psA = (float2*)ps;                    // (p0,p1)
    float2* psB = (float2*)(ps + 2 * rpb);        // (p2,p3)
    float2* psC = (float2*)(ps + 4 * rpb);        // (p4,p5)

    const int bid = blockIdx.x, tid = threadIdx.x;

    // ---- load params into smem (replaces pack kernel + cbank memcpy nodes) ----
    if      (tid < 30)  prm[PW1 + tid]        = W1[tid];
    else if (tid < 110) prm[PW2 + tid - 30]   = W2[tid - 30];
    else if (tid < 113) prm[PB1 + tid - 110]  = b1[tid - 110];
    else if (tid < 116) prm[PGAM + tid - 113] = gam[tid - 113];
    else if (tid < 119) prm[PBET + tid - 116] = bet[tid - 116];
    else if (tid < 125) prm[PM + tid - 119]   = mIn[tid - 119];
    else if (tid < 131) prm[PTH + tid - 125]  = th[tid - 125];
    else if (tid < 139) prm[PG2 + tid - 131]  = g2[tid - 131];
    else if (tid < 147) prm[PBT2 + tid - 139] = bt2[tid - 139];
    else if (tid < 150) prm[PB2 + tid - 147]  = b2[tid - 147];
    __syncthreads();

    const int row0 = bid * rpb;
    int nrows = n - row0;
    if (nrows > rpb) nrows = rpb;
    if (nrows < 0) nrows = 0;

    // fold -log2(e)/(2*theta^2) so fuzzy = ex2(a*a*c2)
    float c2[6], mv[6];
#pragma unroll
    for (int k = 0; k < 6; k++) {
        const float t = prm[PTH + k];
        c2[k] = -1.4426950408889634f / (2.0f * t * t);
        mv[k] = prm[PM + k];
    }
    const float bb1[3] = {prm[PB1], prm[PB1 + 1], prm[PB1 + 2]};
    const float gm[3]  = {prm[PGAM], prm[PGAM + 1], prm[PGAM + 2]};
    const float bt[3]  = {prm[PBET], prm[PBET + 1], prm[PBET + 2]};
    const float2* W1p = (const float2*)(prm + PW1);   // [q*5 + j]

    float2 aS0 = {0,0}, aS1 = {0,0}, aS2 = {0,0}, aS3 = {0,0};
    float2 aQ0 = {0,0}, aQ1 = {0,0}, aQ2 = {0,0}, aQ3 = {0,0};

    const float C2 = 0.99999f * 0.99999f;
    const int ntiles = (nrows + TPB - 1) / TPB;

    // ---------------- Pass 1 (barrier-free): x -> memberships + channel sums ----------------
    for (int t = 0; t < ntiles; t++) {
        const int r = t * TPB + tid;
        if (r < nrows) {
            const float2* xp = (const float2*)(xg + (size_t)(row0 + r) * 10);
            const float2 v0 = xp[0], v1 = xp[1], v2 = xp[2], v3 = xp[3], v4 = xp[4];

            // GEMV1 via pair-dots
            float h[3];
#pragma unroll
            for (int q = 0; q < 3; q++) {
                float2 a = mul2(v0, W1p[q * 5 + 0]);
                a = fma2(v1, W1p[q * 5 + 1], a);
                a = fma2(v2, W1p[q * 5 + 2], a);
                a = fma2(v3, W1p[q * 5 + 3], a);
                a = fma2(v4, W1p[q * 5 + 4], a);
                h[q] = a.x + a.y + bb1[q];
            }
            const float mu = (h[0] + h[1] + h[2]) * (1.0f / 3.0f);
            const float d0 = h[0] - mu, d1 = h[1] - mu, d2 = h[2] - mu;
            const float var = (d0 * d0 + d1 * d1 + d2 * d2) * (1.0f / 3.0f);
            const float rn = rsqrtf(var + 1e-5f);
            const float hn[3] = {fmaf(d0 * rn, gm[0], bt[0]),
                                 fmaf(d1 * rn, gm[1], bt[1]),
                                 fmaf(d2 * rn, gm[2], bt[2])};
            float p[6];
#pragma unroll
            for (int q = 0; q < 3; q++)
#pragma unroll
                for (int j = 0; j < 2; j++) {
                    const int k = q * 2 + j;
                    const float a = hn[q] - mv[k];
                    const float f = ex2f(a * a * c2[k]);
                    const float pv = fminf(f + 1e-16f, C2);
                    p[k] = (q == 0) ? pv : (1.0f - pv);
                }
            psA[r] = make_float2(p[0], p[1]);
            psB[r] = make_float2(p[2], p[3]);
            psC[r] = make_float2(p[4], p[5]);

            const float2 p45 = make_float2(p[4], p[5]);
            const float2 w0 = mul2(splat(p[2]), p45);   // (w00,w01)
            const float2 w1 = mul2(splat(p[3]), p45);   // (w10,w11)
            const float2 o01 = mul2(splat(p[0]), w0);
            const float2 o23 = mul2(splat(p[0]), w1);
            const float2 o45 = mul2(splat(p[1]), w0);
            const float2 o67 = mul2(splat(p[1]), w1);
            aS0 = add2(aS0, o01); aS1 = add2(aS1, o23);
            aS2 = add2(aS2, o45); aS3 = add2(aS3, o67);
            aQ0 = fma2(o01, o01, aQ0); aQ1 = fma2(o23, o23, aQ1);
            aQ2 = fma2(o45, o45, aQ2); aQ3 = fma2(o67, o67, aQ3);
        }
    }

    // ---------------- Block reduction (deterministic) ----------------
    {
        float accA[16] = {aS0.x, aS0.y, aS1.x, aS1.y, aS2.x, aS2.y, aS3.x, aS3.y,
                          aQ0.x, aQ0.y, aQ1.x, aQ1.y, aQ2.x, aQ2.y, aQ3.x, aQ3.y};
        const int lane = tid & 31, wrp = tid >> 5;
#pragma unroll
        for (int k = 0; k < 16; k++) {
            float v = accA[k];
#pragma unroll
            for (int off = 16; off; off >>= 1)
                v += __shfl_down_sync(0xffffffffu, v, off);
            if (lane == 0) red[wrp * 16 + k] = v;
        }
    }
    __syncthreads();
    if (tid < 16) {
        float s = 0.f;
#pragma unroll
        for (int w = 0; w < TPB / 32; w++) s += red[w * 16 + tid];
        g_partials[bid * 16 + tid] = s;
        __threadfence();
    }
    __syncthreads();

    // ---------------- Grid barrier (ticketed, replay-safe) ----------------
    if (tid == 0) {
        __threadfence();
        const unsigned tk = atomicAdd(&g_counter, 1u);
        const unsigned target = (tk / GRID + 1u) * GRID;
        while (*((volatile unsigned*)&g_counter) < target) { }
    }
    __syncthreads();
    __threadfence();

    // ---------------- Finalize BN constants ----------------
    if (tid < 16) {
        float s0 = 0.f, s1 = 0.f, s2v = 0.f, s3 = 0.f;
#pragma unroll 4
        for (int b = 0; b < GRID; b += 4) {
            s0  += __ldcg(&g_partials[(b + 0) * 16 + tid]);
            s1  += __ldcg(&g_partials[(b + 1) * 16 + tid]);
            s2v += __ldcg(&g_partials[(b + 2) * 16 + tid]);
            s3  += __ldcg(&g_partials[(b + 3) * 16 + tid]);
        }
        red[tid] = (s0 + s1) + (s2v + s3);
    }
    __syncthreads();
    if (tid < 8) {
        const float invB = 1.0f / (float)n;
        const float muv = red[tid] * invB;
        const float msq = red[tid + 8] * invB;
        const float var = msq - muv * muv;
        const float sc = prm[PG2 + tid] * rsqrtf(var + 1e-5f);
        s2s[tid] = sc;
        t2s[tid] = prm[PBT2 + tid] - muv * sc;
    }
    __syncthreads();
    if (tid < 3) {
        float a = prm[PB2 + tid];
#pragma unroll
        for (int c = 0; c < 8; c++) a = fmaf(t2s[c], prm[PW2 + tid * 8 + c], a);
        b2p[tid] = a;
    }
    __syncthreads();

    const float2* W2p = (const float2*)(prm + PW2);  // [i*4 + cp]
    const float2* s2p = (const float2*)s2s;
    const float2 sc0 = s2p[0], sc1 = s2p[1], sc2 = s2p[2], sc3 = s2p[3];
    const float bp0 = b2p[0], bp1 = b2p[1], bp2 = b2p[2];

    // ---------------- Pass 2 (barrier-free): memberships -> BN -> logits -> result ----------------
    for (int t = 0; t < ntiles; t++) {
        const int r = t * TPB + tid;
        if (r < nrows) {
            const float2 A = psA[r], Bv = psB[r], p45 = psC[r];
            const float2 w0 = mul2(splat(Bv.x), p45);
            const float2 w1 = mul2(splat(Bv.y), p45);
            const float2 u01 = mul2(mul2(splat(A.x), w0), sc0);
            const float2 u23 = mul2(mul2(splat(A.x), w1), sc1);
            const float2 u45 = mul2(mul2(splat(A.y), w0), sc2);
            const float2 u67 = mul2(mul2(splat(A.y), w1), sc3);

            float lg[3];
            const float bps[3] = {bp0, bp1, bp2};
#pragma unroll
            for (int i = 0; i < 3; i++) {
                float2 a = mul2(u01, W2p[i * 4 + 0]);
                a = fma2(u23, W2p[i * 4 + 1], a);
                a = fma2(u45, W2p[i * 4 + 2], a);
                a = fma2(u67, W2p[i * 4 + 3], a);
                lg[i] = a.x + a.y + bps[i];
            }
            const float sg0 = sin_fast(lg[0] * 0.5f);
            const float sg1 = sin_fast(lg[1] * 0.5f);
            const float sg2 = sin_fast(lg[2] * 0.5f);
            const float pq0 = sg0 * sg0, pq1 = sg1 * sg1, pq2 = sg2 * sg2;
            const float cq0 = 1.f - pq0, cq1 = 1.f - pq1, cq2 = 1.f - pq2;
            const float tt = cq1 * cq2;
            float* dst = outg + (size_t)(row0 + r) * 3;
            dst[0] = cq0 * tt;
            dst[1] = pq0 * tt;
            dst[2] = cq0 * (pq1 * cq2);
        }
    }
}

extern "C" void kernel_launch(void* const* d_in, const int* in_sizes, int n_in,
                              void* d_out, int out_size)
{
    const float* x = (const float*)d_in[0];
    const int n = in_sizes[0] / 10;                 // 1048576
    const int rpb = (n + GRID - 1) / GRID;          // 7085
    const size_t smem = (size_t)(PRM_SZ + 512 + 24 + 6 * rpb) * sizeof(float);
    cudaFuncSetAttribute(qfnn_kernel, cudaFuncAttributeMaxDynamicSharedMemorySize, (int)smem);
    qfnn_kernel<<<GRID, TPB, smem, 0>>>(
        x, (float*)d_out,
        (const float*)d_in[1], (const float*)d_in[2], (const float*)d_in[3],
        (const float*)d_in[4], (const float*)d_in[5], (const float*)d_in[6],
        (const float*)d_in[7], (const float*)d_in[8], (const float*)d_in[9],
        (const float*)d_in[10], n, rpb);
}